// round 1
// baseline (speedup 1.0000x reference)
#include <cuda_runtime.h>
#include <cstdint>

// Problem constants
#define NN 50000
#define EE 500000
#define RR 8
#define HD 128          // IN_DIM == HID == 128
#define NCOLS 1152      // 8*128 relation cols + 128 root cols
#define NG 64
#define NC 16

// ---------------- scratch (device globals; no allocs allowed) ----------------
__device__ float g_xw[(size_t)NN * 1024];      // per-relation transforms [n][r*128+h]
__device__ float g_hacc0[(size_t)NN * HD];     // layer-1 accumulator (root+bias then +agg)
__device__ float g_hacc1[(size_t)NN * HD];     // layer-2 accumulator
__device__ float g_wcat[128 * NCOLS];          // packed [d][c] weight matrix
__device__ int   g_cnt[NN * RR];               // per (dst, rel) edge counts
__device__ float g_pool[NG * HD];              // pooled sums
__device__ float g_pcnt[NG];                   // nodes per graph

// ---------------- small utility kernels ----------------
__global__ void zero_int_kernel(int n) {
    int i = blockIdx.x * blockDim.x + threadIdx.x;
    if (i < n) g_cnt[i] = 0;
}

__global__ void zero_pool_kernel() {
    int i = blockIdx.x * blockDim.x + threadIdx.x;
    if (i < NG * HD) g_pool[i] = 0.0f;
    if (i < NG) g_pcnt[i] = 0.0f;
}

__global__ void count_kernel(const int* __restrict__ dst, const int* __restrict__ rel) {
    int e = blockIdx.x * blockDim.x + threadIdx.x;
    if (e < EE) atomicAdd(&g_cnt[dst[e] * RR + rel[e]], 1);
}

// pack Wcat[d][c]: c<1024 -> W[r][d][h] with r=c>>7,h=c&127; c>=1024 -> root[d][c-1024]
__global__ void pack_w_kernel(const float* __restrict__ W, const float* __restrict__ root) {
    int i = blockIdx.x * blockDim.x + threadIdx.x;
    if (i >= 128 * NCOLS) return;
    int d = i / NCOLS, c = i % NCOLS;
    float v;
    if (c < 1024) {
        int r = c >> 7, h = c & 127;
        v = W[((size_t)r * 128 + d) * 128 + h];
    } else {
        v = root[(size_t)d * 128 + (c - 1024)];
    }
    g_wcat[i] = v;
}

// ---------------- GEMM: A[M,128] @ Wcat[128,1152] ----------------
// Relation cols (ctile 0..7) -> g_xw[n][ctile*128 + col]
// Root cols (ctile 8)        -> hacc[n][col] = acc + bias[col]
// layer==0: A = x input (no relu);  layer==1: A = relu(g_hacc0)
__global__ __launch_bounds__(256, 2)
void gemm_kernel(const float* __restrict__ x_in, const float* __restrict__ bias, int layer) {
    const float* __restrict__ A = (layer == 0) ? x_in : g_hacc0;
    float* __restrict__ outroot = (layer == 0) ? g_hacc0 : g_hacc1;

    __shared__ float As[16][132];   // [k][m], padded
    __shared__ float Bs[16][128];   // [k][n]

    const int ctile = blockIdx.x;           // 0..8
    const int mbase = blockIdx.y * 128;
    const int tid = threadIdx.x;             // 256
    const int tx = tid & 15, ty = tid >> 4;  // 16x16 thread grid, 8x8 micro-tile
    const bool relu = (layer != 0);

    float acc[8][8];
    #pragma unroll
    for (int i = 0; i < 8; i++)
        #pragma unroll
        for (int j = 0; j < 8; j++) acc[i][j] = 0.0f;

    for (int k0 = 0; k0 < 128; k0 += 16) {
        // Load A chunk: 128 rows x 16 k = 512 float4
        #pragma unroll
        for (int it = 0; it < 2; it++) {
            int idx = tid + it * 256;          // 0..511
            int arow = idx >> 2;               // 0..127
            int acol = (idx & 3) * 4;          // 0,4,8,12
            int m = mbase + arow;
            float4 v = make_float4(0.f, 0.f, 0.f, 0.f);
            if (m < NN) v = *(const float4*)(A + (size_t)m * 128 + k0 + acol);
            if (relu) {
                v.x = fmaxf(v.x, 0.f); v.y = fmaxf(v.y, 0.f);
                v.z = fmaxf(v.z, 0.f); v.w = fmaxf(v.w, 0.f);
            }
            As[acol + 0][arow] = v.x;
            As[acol + 1][arow] = v.y;
            As[acol + 2][arow] = v.z;
            As[acol + 3][arow] = v.w;
        }
        // Load B chunk: 16 k x 128 n = 512 float4
        #pragma unroll
        for (int it = 0; it < 2; it++) {
            int idx = tid + it * 256;
            int brow = idx >> 5;                // 0..15
            int bcol = (idx & 31) * 4;          // 0..124
            float4 v = *(const float4*)(g_wcat + (size_t)(k0 + brow) * NCOLS + ctile * 128 + bcol);
            *(float4*)&Bs[brow][bcol] = v;
        }
        __syncthreads();

        #pragma unroll
        for (int k = 0; k < 16; k++) {
            float ra[8], rb[8];
            *(float4*)&ra[0] = *(const float4*)&As[k][ty * 8];
            *(float4*)&ra[4] = *(const float4*)&As[k][ty * 8 + 4];
            *(float4*)&rb[0] = *(const float4*)&Bs[k][tx * 8];
            *(float4*)&rb[4] = *(const float4*)&Bs[k][tx * 8 + 4];
            #pragma unroll
            for (int i = 0; i < 8; i++)
                #pragma unroll
                for (int j = 0; j < 8; j++)
                    acc[i][j] = fmaf(ra[i], rb[j], acc[i][j]);
        }
        __syncthreads();
    }

    if (ctile < 8) {
        #pragma unroll
        for (int i = 0; i < 8; i++) {
            int m = mbase + ty * 8 + i;
            if (m < NN) {
                float* o = g_xw + (size_t)m * 1024 + ctile * 128 + tx * 8;
                *(float4*)(o + 0) = make_float4(acc[i][0], acc[i][1], acc[i][2], acc[i][3]);
                *(float4*)(o + 4) = make_float4(acc[i][4], acc[i][5], acc[i][6], acc[i][7]);
            }
        }
    } else {
        #pragma unroll
        for (int i = 0; i < 8; i++) {
            int m = mbase + ty * 8 + i;
            if (m < NN) {
                float* o = outroot + (size_t)m * 128 + tx * 8;
                #pragma unroll
                for (int j = 0; j < 8; j++) o[j] = acc[i][j] + bias[tx * 8 + j];
            }
        }
    }
}

// ---------------- edge aggregation: one warp per edge ----------------
// hacc[dst] += (1/max(cnt[dst,rel],1)) * g_xw[src][rel*128 ...]
__global__ void edge_agg_kernel(const int* __restrict__ src, const int* __restrict__ dst,
                                const int* __restrict__ rel, int layer) {
    float* __restrict__ hacc = (layer == 0) ? g_hacc0 : g_hacc1;
    int gwarp = (blockIdx.x * blockDim.x + threadIdx.x) >> 5;
    int lane = threadIdx.x & 31;
    if (gwarp >= EE) return;
    int s = src[gwarp];
    int d = dst[gwarp];
    int r = rel[gwarp];
    int c = g_cnt[d * RR + r];
    float coef = 1.0f / (float)max(c, 1);
    float4 v = *(const float4*)(g_xw + (size_t)s * 1024 + r * 128 + lane * 4);
    float* o = hacc + (size_t)d * 128 + lane * 4;
    atomicAdd(o + 0, v.x * coef);
    atomicAdd(o + 1, v.y * coef);
    atomicAdd(o + 2, v.z * coef);
    atomicAdd(o + 3, v.w * coef);
}

// ---------------- pooling: sum relu(h2) per graph ----------------
__global__ void pool_kernel(const int* __restrict__ batch) {
    int i = blockIdx.x * blockDim.x + threadIdx.x;
    if (i >= NN * HD) return;
    int n = i >> 7, h = i & 127;
    float v = fmaxf(g_hacc1[i], 0.0f);
    int g = batch[n];
    atomicAdd(&g_pool[g * HD + h], v);
    if (h == 0) atomicAdd(&g_pcnt[g], 1.0f);
}

// ---------------- head: out[g][c] = (pool[g]/cnt[g]) @ linW + linb ----------------
__global__ void final_kernel(const float* __restrict__ linW, const float* __restrict__ linb,
                             float* __restrict__ out) {
    int g = blockIdx.x;
    int tid = threadIdx.x;  // 128
    __shared__ float p[HD];
    float cnt = fmaxf(g_pcnt[g], 1.0f);
    p[tid] = g_pool[g * HD + tid] / cnt;
    __syncthreads();
    if (tid < NC) {
        float s = linb[tid];
        #pragma unroll 8
        for (int h = 0; h < HD; h++) s = fmaf(p[h], linW[h * NC + tid], s);
        out[g * NC + tid] = s;
    }
}

// ---------------- launch ----------------
extern "C" void kernel_launch(void* const* d_in, const int* in_sizes, int n_in,
                              void* d_out, int out_size) {
    const float* x     = (const float*)d_in[0];
    const int*   eidx  = (const int*)d_in[1];   // [2,E]: first E = src, next E = dst
    const int*   etype = (const int*)d_in[2];
    const int*   batch = (const int*)d_in[3];
    const float* W1    = (const float*)d_in[4];
    const float* root1 = (const float*)d_in[5];
    const float* b1    = (const float*)d_in[6];
    const float* W2    = (const float*)d_in[7];
    const float* root2 = (const float*)d_in[8];
    const float* b2    = (const float*)d_in[9];
    const float* linW  = (const float*)d_in[10];
    const float* linb  = (const float*)d_in[11];
    float* out = (float*)d_out;

    const int* src = eidx;
    const int* dst = eidx + EE;

    // structure-dependent counts (shared by both layers)
    zero_int_kernel<<<(NN * RR + 255) / 256, 256>>>(NN * RR);
    count_kernel<<<(EE + 255) / 256, 256>>>(dst, etype);

    dim3 ggrid(9, (NN + 127) / 128);
    int edge_blocks = (EE * 32 + 255) / 256;

    // layer 1
    pack_w_kernel<<<(128 * NCOLS + 255) / 256, 256>>>(W1, root1);
    gemm_kernel<<<ggrid, 256>>>(x, b1, 0);
    edge_agg_kernel<<<edge_blocks, 256>>>(src, dst, etype, 0);

    // layer 2 (relu of layer-1 fused into GEMM A-load)
    pack_w_kernel<<<(128 * NCOLS + 255) / 256, 256>>>(W2, root2);
    gemm_kernel<<<ggrid, 256>>>(x, b2, 1);
    edge_agg_kernel<<<edge_blocks, 256>>>(src, dst, etype, 1);

    // pooling + head (relu of layer-2 fused into pooling read)
    zero_pool_kernel<<<(NG * HD + 255) / 256, 256>>>();
    pool_kernel<<<(NN * HD + 255) / 256, 256>>>(batch);
    final_kernel<<<NG, 128>>>(linW, linb, out);
}

// round 3
// speedup vs baseline: 1.6125x; 1.6125x over previous
#include <cuda_runtime.h>
#include <cuda_bf16.h>
#include <cstdint>

// Problem constants
#define NN 50000
#define EE 500000
#define RR 8
#define HD 128
#define NG 64
#define NC 16
#define NTILES ((NN + 127) / 128)   // 391

// ---------------- scratch (device globals; no allocs allowed) ----------------
__device__ float g_xw[(size_t)NN * 1024];      // per-relation transforms [n][r*128+h]
__device__ float g_hacc0[(size_t)NN * HD];     // layer-1 accumulator
__device__ float g_hacc1[(size_t)NN * HD];     // layer-2 accumulator
__device__ __align__(16) __nv_bfloat16 g_wh[9 * 128 * 128];  // weight hi, [ct][n][k]
__device__ __align__(16) __nv_bfloat16 g_wl[9 * 128 * 128];  // weight lo, [ct][n][k]
__device__ int   g_cnt[NN * RR];
__device__ float g_pool[NG * HD];
__device__ float g_pcnt[NG];

// ---------------- helpers ----------------
__device__ __forceinline__ uint32_t smem_to_u32(const void* p) {
    uint32_t a;
    asm("{ .reg .u64 t; cvta.to.shared.u64 t, %1; cvt.u32.u64 %0, t; }" : "=r"(a) : "l"(p));
    return a;
}
__device__ __forceinline__ uint32_t pack_bf2(__nv_bfloat16 a, __nv_bfloat16 b) {
    __nv_bfloat162 t = __halves2bfloat162(a, b);
    return *reinterpret_cast<uint32_t*>(&t);
}
__device__ __forceinline__ void split_bf(float v, __nv_bfloat16& h, __nv_bfloat16& l) {
    h = __float2bfloat16(v);
    l = __float2bfloat16(v - __bfloat162float(h));
}
__device__ __forceinline__ void cp16(uint32_t dst, const void* src) {
    asm volatile("cp.async.cg.shared.global [%0], [%1], 16;" :: "r"(dst), "l"(src));
}
#define CP_COMMIT() asm volatile("cp.async.commit_group;" ::: "memory")
#define CP_WAIT0()  asm volatile("cp.async.wait_group 0;" ::: "memory")

__device__ __forceinline__ void ldsm_x4(uint32_t addr, uint32_t& r0, uint32_t& r1,
                                        uint32_t& r2, uint32_t& r3) {
    asm volatile("ldmatrix.sync.aligned.m8n8.x4.shared.b16 {%0,%1,%2,%3}, [%4];"
                 : "=r"(r0), "=r"(r1), "=r"(r2), "=r"(r3) : "r"(addr));
}
__device__ __forceinline__ void mma16816(float* c, const uint32_t* a, const uint32_t* b) {
    asm volatile("mma.sync.aligned.m16n8k16.row.col.f32.bf16.bf16.f32 "
                 "{%0,%1,%2,%3}, {%4,%5,%6,%7}, {%8,%9}, {%0,%1,%2,%3};"
                 : "+f"(c[0]), "+f"(c[1]), "+f"(c[2]), "+f"(c[3])
                 : "r"(a[0]), "r"(a[1]), "r"(a[2]), "r"(a[3]), "r"(b[0]), "r"(b[1]));
}

// smem layout (bytes): padded rows 136 bf16 = 272 B
#define ROWB 272
#define ATILE 34816                 // 128*272
#define SM_A_HI 0
#define SM_A_LO 34816
#define SM_B    69632               // two buffers of (hi 34816 + lo 34816)
#define BBUF    69632
#define SMEM_TOTAL (3 * 69632)      // 208896

// ---------------- small utility kernels ----------------
__global__ void zero_int_kernel(int n) {
    int i = blockIdx.x * blockDim.x + threadIdx.x;
    if (i < n) g_cnt[i] = 0;
}
__global__ void zero_pool_kernel() {
    int i = blockIdx.x * blockDim.x + threadIdx.x;
    if (i < NG * HD) g_pool[i] = 0.0f;
    if (i < NG) g_pcnt[i] = 0.0f;
}
__global__ void count_kernel(const int* __restrict__ dst, const int* __restrict__ rel) {
    int e = blockIdx.x * blockDim.x + threadIdx.x;
    if (e < EE) atomicAdd(&g_cnt[dst[e] * RR + rel[e]], 1);
}

// pack weights: split fp32 -> bf16 hi/lo, layout [ct][n][k] (col-major for mma row.col)
__global__ void pack_w_kernel(const float* __restrict__ W, const float* __restrict__ root) {
    int i = blockIdx.x * blockDim.x + threadIdx.x;
    if (i >= 9 * 128 * 128) return;
    int ct = i >> 14;
    int rem = i & 16383;
    int n = rem >> 7;
    int k = rem & 127;
    float v = (ct < 8) ? W[((size_t)ct * 128 + k) * 128 + n] : root[(size_t)k * 128 + n];
    __nv_bfloat16 h, l;
    split_bf(v, h, l);
    g_wh[i] = h;
    g_wl[i] = l;
}

// ---------------- mma.sync split-bf16 GEMM: A[M,128] @ Wcat[128,1152] ----------------
// ctile 0..7 -> g_xw[m][ct*128+col];  ctile 8 -> hacc[m][col] = acc + bias[col]
__global__ __launch_bounds__(256, 1)
void gemm_mma_kernel(const float* __restrict__ x_in, const float* __restrict__ bias, int layer) {
    extern __shared__ char smem[];
    const float* __restrict__ A = (layer == 0) ? x_in : g_hacc0;
    float* __restrict__ outroot = (layer == 0) ? g_hacc0 : g_hacc1;
    const bool relu = (layer != 0);

    const int tid = threadIdx.x;
    const int wid = tid >> 5, lane = tid & 31;
    const int warp_m = wid >> 2;          // 0..1  (64 rows each)
    const int warp_n = wid & 3;           // 0..3  (32 cols each)
    const int mt = blockIdx.x;
    const uint32_t su = smem_to_u32(smem);

    // per-lane ldmatrix byte offsets
    const uint32_t a_lane = (uint32_t)(warp_m * 64 + ((lane >> 3) & 1) * 8 + (lane & 7)) * ROWB
                          + (uint32_t)(lane >> 4) * 16;
    const uint32_t b_lane = (uint32_t)(warp_n * 32 + ((lane >> 4) & 1) * 8 + (lane & 7)) * ROWB
                          + (uint32_t)((lane >> 3) & 1) * 16;

    // bias pairs for ct==8 epilogue
    float2 bv[4];
    #pragma unroll
    for (int ni = 0; ni < 4; ni++)
        bv[ni] = *(const float2*)(bias + warp_n * 32 + ni * 8 + (lane & 3) * 2);

    // ---- load + split A tile (once per block) ----
    {
        int row = tid >> 1;
        int kh = (tid & 1) * 64;
        int m = mt * 128 + row;
        const float* ap = A + (size_t)m * 128 + kh;
        char* dh = smem + SM_A_HI + row * ROWB + kh * 2;
        char* dl = smem + SM_A_LO + row * ROWB + kh * 2;
        #pragma unroll
        for (int j = 0; j < 16; j++) {
            float4 v = make_float4(0.f, 0.f, 0.f, 0.f);
            if (m < NN) v = *(const float4*)(ap + 4 * j);
            if (relu) {
                v.x = fmaxf(v.x, 0.f); v.y = fmaxf(v.y, 0.f);
                v.z = fmaxf(v.z, 0.f); v.w = fmaxf(v.w, 0.f);
            }
            __nv_bfloat16 h0, l0, h1, l1, h2, l2, h3, l3;
            split_bf(v.x, h0, l0); split_bf(v.y, h1, l1);
            split_bf(v.z, h2, l2); split_bf(v.w, h3, l3);
            *(uint32_t*)(dh + 8 * j)     = pack_bf2(h0, h1);
            *(uint32_t*)(dh + 8 * j + 4) = pack_bf2(h2, h3);
            *(uint32_t*)(dl + 8 * j)     = pack_bf2(l0, l1);
            *(uint32_t*)(dl + 8 * j + 4) = pack_bf2(l2, l3);
        }
    }

    // ---- prefetch B(ct=0) into buffer 0 ----
    {
        int n = tid >> 1, half = tid & 1;
        const char* sh = (const char*)g_wh + ((size_t)0 * 16384 + n * 128 + half * 64) * 2;
        const char* sl = (const char*)g_wl + ((size_t)0 * 16384 + n * 128 + half * 64) * 2;
        uint32_t dh = su + SM_B + n * ROWB + half * 128;
        uint32_t dl = dh + ATILE;
        #pragma unroll
        for (int j = 0; j < 8; j++) { cp16(dh + 16 * j, sh + 16 * j); cp16(dl + 16 * j, sl + 16 * j); }
        CP_COMMIT();
    }
    CP_WAIT0();
    __syncthreads();

    for (int ct = 0; ct < 9; ct++) {
        int buf = ct & 1;
        // prefetch next B into the other buffer
        if (ct < 8) {
            int n = tid >> 1, half = tid & 1;
            const char* sh = (const char*)g_wh + ((size_t)(ct + 1) * 16384 + n * 128 + half * 64) * 2;
            const char* sl = (const char*)g_wl + ((size_t)(ct + 1) * 16384 + n * 128 + half * 64) * 2;
            uint32_t dh = su + SM_B + (buf ^ 1) * BBUF + n * ROWB + half * 128;
            uint32_t dl = dh + ATILE;
            #pragma unroll
            for (int j = 0; j < 8; j++) { cp16(dh + 16 * j, sh + 16 * j); cp16(dl + 16 * j, sl + 16 * j); }
            CP_COMMIT();
        }

        // ---- compute 128x128 tile: 3 passes (Ah*Bh + Ah*Bl + Al*Bh) ----
        float c[4][4][4];
        #pragma unroll
        for (int mi = 0; mi < 4; mi++)
            #pragma unroll
            for (int ni = 0; ni < 4; ni++)
                #pragma unroll
                for (int q = 0; q < 4; q++) c[mi][ni][q] = 0.0f;

        const uint32_t bbase = su + SM_B + buf * BBUF;
        #pragma unroll
        for (int pass = 0; pass < 3; pass++) {
            const uint32_t as = su + ((pass == 2) ? SM_A_LO : SM_A_HI) + a_lane;
            const uint32_t bs = bbase + ((pass == 1) ? ATILE : 0) + b_lane;
            #pragma unroll
            for (int k0 = 0; k0 < 128; k0 += 16) {
                uint32_t a[4][4];
                #pragma unroll
                for (int mi = 0; mi < 4; mi++)
                    ldsm_x4(as + mi * (16 * ROWB) + k0 * 2,
                            a[mi][0], a[mi][1], a[mi][2], a[mi][3]);
                uint32_t b[4][2];
                #pragma unroll
                for (int p = 0; p < 2; p++) {
                    uint32_t r0, r1, r2, r3;
                    ldsm_x4(bs + p * (16 * ROWB) + k0 * 2, r0, r1, r2, r3);
                    b[2 * p][0] = r0; b[2 * p][1] = r1;
                    b[2 * p + 1][0] = r2; b[2 * p + 1][1] = r3;
                }
                #pragma unroll
                for (int mi = 0; mi < 4; mi++)
                    #pragma unroll
                    for (int ni = 0; ni < 4; ni++)
                        mma16816(c[mi][ni], a[mi], b[ni]);
            }
        }

        // ---- epilogue ----
        #pragma unroll
        for (int mi = 0; mi < 4; mi++) {
            int row0 = mt * 128 + warp_m * 64 + mi * 16 + (lane >> 2);
            int row1 = row0 + 8;
            #pragma unroll
            for (int ni = 0; ni < 4; ni++) {
                int col = warp_n * 32 + ni * 8 + (lane & 3) * 2;
                if (ct < 8) {
                    if (row0 < NN)
                        *(float2*)(g_xw + (size_t)row0 * 1024 + ct * 128 + col) =
                            make_float2(c[mi][ni][0], c[mi][ni][1]);
                    if (row1 < NN)
                        *(float2*)(g_xw + (size_t)row1 * 1024 + ct * 128 + col) =
                            make_float2(c[mi][ni][2], c[mi][ni][3]);
                } else {
                    if (row0 < NN)
                        *(float2*)(outroot + (size_t)row0 * 128 + col) =
                            make_float2(c[mi][ni][0] + bv[ni].x, c[mi][ni][1] + bv[ni].y);
                    if (row1 < NN)
                        *(float2*)(outroot + (size_t)row1 * 128 + col) =
                            make_float2(c[mi][ni][2] + bv[ni].x, c[mi][ni][3] + bv[ni].y);
                }
            }
        }

        CP_WAIT0();
        __syncthreads();
    }
}

// ---------------- edge aggregation: one warp per edge, vector red ----------------
__global__ void edge_agg_kernel(const int* __restrict__ src, const int* __restrict__ dst,
                                const int* __restrict__ rel, int layer) {
    float* __restrict__ hacc = (layer == 0) ? g_hacc0 : g_hacc1;
    int gwarp = (blockIdx.x * blockDim.x + threadIdx.x) >> 5;
    int lane = threadIdx.x & 31;
    if (gwarp >= EE) return;
    int s = src[gwarp];
    int d = dst[gwarp];
    int r = rel[gwarp];
    int c = g_cnt[d * RR + r];
    float coef = 1.0f / (float)max(c, 1);
    float4 v = *(const float4*)(g_xw + (size_t)s * 1024 + r * 128 + lane * 4);
    float* o = hacc + (size_t)d * 128 + lane * 4;
    asm volatile("red.global.add.v4.f32 [%0], {%1, %2, %3, %4};"
                 :: "l"(o), "f"(v.x * coef), "f"(v.y * coef), "f"(v.z * coef), "f"(v.w * coef)
                 : "memory");
}

// ---------------- pooling: sum relu(h2) per graph ----------------
__global__ void pool_kernel(const int* __restrict__ batch) {
    int i = blockIdx.x * blockDim.x + threadIdx.x;
    if (i >= NN * HD) return;
    int n = i >> 7, h = i & 127;
    float v = fmaxf(g_hacc1[i], 0.0f);
    int g = batch[n];
    atomicAdd(&g_pool[g * HD + h], v);
    if (h == 0) atomicAdd(&g_pcnt[g], 1.0f);
}

// ---------------- head ----------------
__global__ void final_kernel(const float* __restrict__ linW, const float* __restrict__ linb,
                             float* __restrict__ out) {
    int g = blockIdx.x;
    int tid = threadIdx.x;  // 128
    __shared__ float p[HD];
    float cnt = fmaxf(g_pcnt[g], 1.0f);
    p[tid] = g_pool[g * HD + tid] / cnt;
    __syncthreads();
    if (tid < NC) {
        float s = linb[tid];
        #pragma unroll 8
        for (int h = 0; h < HD; h++) s = fmaf(p[h], linW[h * NC + tid], s);
        out[g * NC + tid] = s;
    }
}

// ---------------- launch ----------------
extern "C" void kernel_launch(void* const* d_in, const int* in_sizes, int n_in,
                              void* d_out, int out_size) {
    const float* x     = (const float*)d_in[0];
    const int*   eidx  = (const int*)d_in[1];
    const int*   etype = (const int*)d_in[2];
    const int*   batch = (const int*)d_in[3];
    const float* W1    = (const float*)d_in[4];
    const float* root1 = (const float*)d_in[5];
    const float* b1    = (const float*)d_in[6];
    const float* W2    = (const float*)d_in[7];
    const float* root2 = (const float*)d_in[8];
    const float* b2    = (const float*)d_in[9];
    const float* linW  = (const float*)d_in[10];
    const float* linb  = (const float*)d_in[11];
    float* out = (float*)d_out;

    const int* src = eidx;
    const int* dst = eidx + EE;

    static bool attr_done = false;
    if (!attr_done) {
        cudaFuncSetAttribute(gemm_mma_kernel, cudaFuncAttributeMaxDynamicSharedMemorySize, SMEM_TOTAL);
        attr_done = true;
    }

    // structure-dependent counts (shared by both layers)
    zero_int_kernel<<<(NN * RR + 255) / 256, 256>>>(NN * RR);
    count_kernel<<<(EE + 255) / 256, 256>>>(dst, etype);

    int edge_blocks = (EE * 32 + 255) / 256;
    int pack_blocks = (9 * 128 * 128 + 255) / 256;

    // layer 1
    pack_w_kernel<<<pack_blocks, 256>>>(W1, root1);
    gemm_mma_kernel<<<NTILES, 256, SMEM_TOTAL>>>(x, b1, 0);
    edge_agg_kernel<<<edge_blocks, 256>>>(src, dst, etype, 0);

    // layer 2 (relu of layer-1 fused into GEMM A-load)
    pack_w_kernel<<<pack_blocks, 256>>>(W2, root2);
    gemm_mma_kernel<<<NTILES, 256, SMEM_TOTAL>>>(x, b2, 1);
    edge_agg_kernel<<<edge_blocks, 256>>>(src, dst, etype, 1);

    // pooling + head (relu of layer-2 fused into pooling read)
    zero_pool_kernel<<<(NG * HD + 255) / 256, 256>>>();
    pool_kernel<<<(NN * HD + 255) / 256, 256>>>(batch);
    final_kernel<<<NG, 128>>>(linW, linb, out);
}

// round 4
// speedup vs baseline: 1.6600x; 1.0295x over previous
#include <cuda_runtime.h>
#include <cuda_bf16.h>
#include <cstdint>

// Problem constants
#define NN 50000
#define EE 500000
#define RR 8
#define HD 128
#define NG 64
#define NC 16
#define NTILES ((NN + 127) / 128)   // 391

// ---------------- scratch (device globals; no allocs allowed) ----------------
__device__ float g_xw[(size_t)NN * 1024];      // per-relation transforms [n][r*128+h]
__device__ float g_hacc0[(size_t)NN * HD];     // layer-1 accumulator
__device__ float g_hacc1[(size_t)NN * HD];     // layer-2 accumulator
__device__ __align__(16) __nv_bfloat16 g_wh[9 * 128 * 128];  // weight hi, [ct][n][k]
__device__ __align__(16) __nv_bfloat16 g_wl[9 * 128 * 128];  // weight lo, [ct][n][k]
__device__ int   g_cnt[NN * RR];
__device__ float g_pool[NG * HD];
__device__ float g_pcnt[NG];

// ---------------- helpers ----------------
__device__ __forceinline__ uint32_t smem_to_u32(const void* p) {
    uint32_t a;
    asm("{ .reg .u64 t; cvta.to.shared.u64 t, %1; cvt.u32.u64 %0, t; }" : "=r"(a) : "l"(p));
    return a;
}
__device__ __forceinline__ uint32_t pack_bf2(__nv_bfloat16 a, __nv_bfloat16 b) {
    __nv_bfloat162 t = __halves2bfloat162(a, b);
    return *reinterpret_cast<uint32_t*>(&t);
}
__device__ __forceinline__ void split_bf(float v, __nv_bfloat16& h, __nv_bfloat16& l) {
    h = __float2bfloat16(v);
    l = __float2bfloat16(v - __bfloat162float(h));
}
__device__ __forceinline__ void cp16(uint32_t dst, const void* src) {
    asm volatile("cp.async.cg.shared.global [%0], [%1], 16;" :: "r"(dst), "l"(src));
}
#define CP_COMMIT() asm volatile("cp.async.commit_group;" ::: "memory")
#define CP_WAIT0()  asm volatile("cp.async.wait_group 0;" ::: "memory")

__device__ __forceinline__ void ldsm_x4(uint32_t addr, uint32_t& r0, uint32_t& r1,
                                        uint32_t& r2, uint32_t& r3) {
    asm volatile("ldmatrix.sync.aligned.m8n8.x4.shared.b16 {%0,%1,%2,%3}, [%4];"
                 : "=r"(r0), "=r"(r1), "=r"(r2), "=r"(r3) : "r"(addr));
}
__device__ __forceinline__ void mma16816(float* c, const uint32_t* a, const uint32_t* b) {
    asm volatile("mma.sync.aligned.m16n8k16.row.col.f32.bf16.bf16.f32 "
                 "{%0,%1,%2,%3}, {%4,%5,%6,%7}, {%8,%9}, {%0,%1,%2,%3};"
                 : "+f"(c[0]), "+f"(c[1]), "+f"(c[2]), "+f"(c[3])
                 : "r"(a[0]), "r"(a[1]), "r"(a[2]), "r"(a[3]), "r"(b[0]), "r"(b[1]));
}

// smem layout (bytes): padded rows 136 bf16 = 272 B
#define ROWB 272
#define ATILE 34816                 // 128*272
#define SM_A_HI 0
#define SM_A_LO 34816
#define SM_B    69632               // two buffers of (hi 34816 + lo 34816)
#define BBUF    69632
#define SMEM_TOTAL (3 * 69632)      // 208896

// ---------------- small utility kernels ----------------
__global__ void zero_int_kernel(int n) {
    int i = blockIdx.x * blockDim.x + threadIdx.x;
    if (i < n) g_cnt[i] = 0;
}
__global__ void zero_pool_kernel() {
    int i = blockIdx.x * blockDim.x + threadIdx.x;
    if (i < NG * HD) g_pool[i] = 0.0f;
    if (i < NG) g_pcnt[i] = 0.0f;
}
__global__ void count_kernel(const int* __restrict__ dst, const int* __restrict__ rel) {
    int e = blockIdx.x * blockDim.x + threadIdx.x;
    if (e < EE) atomicAdd(&g_cnt[dst[e] * RR + rel[e]], 1);
}

// pack weights: split fp32 -> bf16 hi/lo, layout [ct][n][k] (col-major for mma row.col)
__global__ void pack_w_kernel(const float* __restrict__ W, const float* __restrict__ root) {
    int i = blockIdx.x * blockDim.x + threadIdx.x;
    if (i >= 9 * 128 * 128) return;
    int ct = i >> 14;
    int rem = i & 16383;
    int n = rem >> 7;
    int k = rem & 127;
    float v = (ct < 8) ? W[((size_t)ct * 128 + k) * 128 + n] : root[(size_t)k * 128 + n];
    __nv_bfloat16 h, l;
    split_bf(v, h, l);
    g_wh[i] = h;
    g_wl[i] = l;
}

// ---------------- mma.sync split-bf16 GEMM: A[M,128] @ Wcat[128,1152] ----------------
// Fused 3-product k-loop with register double-buffered fragments.
__global__ __launch_bounds__(256, 1)
void gemm_mma_kernel(const float* __restrict__ x_in, const float* __restrict__ bias, int layer) {
    extern __shared__ char smem[];
    const float* __restrict__ A = (layer == 0) ? x_in : g_hacc0;
    float* __restrict__ outroot = (layer == 0) ? g_hacc0 : g_hacc1;
    const bool relu = (layer != 0);

    const int tid = threadIdx.x;
    const int wid = tid >> 5, lane = tid & 31;
    const int warp_m = wid >> 2;          // 0..1  (64 rows each)
    const int warp_n = wid & 3;           // 0..3  (32 cols each)
    const int mt = blockIdx.x;
    const uint32_t su = smem_to_u32(smem);

    // per-lane ldmatrix byte offsets
    const uint32_t a_lane = (uint32_t)(warp_m * 64 + ((lane >> 3) & 1) * 8 + (lane & 7)) * ROWB
                          + (uint32_t)(lane >> 4) * 16;
    const uint32_t b_lane = (uint32_t)(warp_n * 32 + ((lane >> 4) & 1) * 8 + (lane & 7)) * ROWB
                          + (uint32_t)((lane >> 3) & 1) * 16;

    // bias pairs for ct==8 epilogue
    float2 bv[4];
    #pragma unroll
    for (int ni = 0; ni < 4; ni++)
        bv[ni] = *(const float2*)(bias + warp_n * 32 + ni * 8 + (lane & 3) * 2);

    // ---- load + split A tile (once per block) ----
    {
        int row = tid >> 1;
        int kh = (tid & 1) * 64;
        int m = mt * 128 + row;
        const float* ap = A + (size_t)m * 128 + kh;
        char* dh = smem + SM_A_HI + row * ROWB + kh * 2;
        char* dl = smem + SM_A_LO + row * ROWB + kh * 2;
        #pragma unroll
        for (int j = 0; j < 16; j++) {
            float4 v = make_float4(0.f, 0.f, 0.f, 0.f);
            if (m < NN) v = *(const float4*)(ap + 4 * j);
            if (relu) {
                v.x = fmaxf(v.x, 0.f); v.y = fmaxf(v.y, 0.f);
                v.z = fmaxf(v.z, 0.f); v.w = fmaxf(v.w, 0.f);
            }
            __nv_bfloat16 h0, l0, h1, l1, h2, l2, h3, l3;
            split_bf(v.x, h0, l0); split_bf(v.y, h1, l1);
            split_bf(v.z, h2, l2); split_bf(v.w, h3, l3);
            *(uint32_t*)(dh + 8 * j)     = pack_bf2(h0, h1);
            *(uint32_t*)(dh + 8 * j + 4) = pack_bf2(h2, h3);
            *(uint32_t*)(dl + 8 * j)     = pack_bf2(l0, l1);
            *(uint32_t*)(dl + 8 * j + 4) = pack_bf2(l2, l3);
        }
    }

    // ---- prefetch B(ct=0) into buffer 0 ----
    {
        int n = tid >> 1, half = tid & 1;
        const char* sh = (const char*)g_wh + ((size_t)0 * 16384 + n * 128 + half * 64) * 2;
        const char* sl = (const char*)g_wl + ((size_t)0 * 16384 + n * 128 + half * 64) * 2;
        uint32_t dh = su + SM_B + n * ROWB + half * 128;
        uint32_t dl = dh + ATILE;
        #pragma unroll
        for (int j = 0; j < 8; j++) { cp16(dh + 16 * j, sh + 16 * j); cp16(dl + 16 * j, sl + 16 * j); }
        CP_COMMIT();
    }
    CP_WAIT0();
    __syncthreads();

    for (int ct = 0; ct < 9; ct++) {
        int buf = ct & 1;
        // prefetch next B into the other buffer
        if (ct < 8) {
            int n = tid >> 1, half = tid & 1;
            const char* sh = (const char*)g_wh + ((size_t)(ct + 1) * 16384 + n * 128 + half * 64) * 2;
            const char* sl = (const char*)g_wl + ((size_t)(ct + 1) * 16384 + n * 128 + half * 64) * 2;
            uint32_t dh = su + SM_B + (buf ^ 1) * BBUF + n * ROWB + half * 128;
            uint32_t dl = dh + ATILE;
            #pragma unroll
            for (int j = 0; j < 8; j++) { cp16(dh + 16 * j, sh + 16 * j); cp16(dl + 16 * j, sl + 16 * j); }
            CP_COMMIT();
        }

        // ---- compute 128x128 tile: fused (Ah*Bh + Ah*Bl + Al*Bh) per k-step ----
        float c[4][4][4];
        #pragma unroll
        for (int mi = 0; mi < 4; mi++)
            #pragma unroll
            for (int ni = 0; ni < 4; ni++)
                #pragma unroll
                for (int q = 0; q < 4; q++) c[mi][ni][q] = 0.0f;

        const uint32_t bbase = su + SM_B + buf * BBUF;
        const uint32_t as_h = su + SM_A_HI + a_lane;
        const uint32_t as_l = su + SM_A_LO + a_lane;
        const uint32_t bs_h = bbase + b_lane;
        const uint32_t bs_l = bbase + ATILE + b_lane;

        uint32_t ah[2][4][4], al[2][4][4], bh[2][4][2], bl[2][4][2];

        // fragment-load macro: slot s, k-offset in bytes
        #define LOAD_FRAGS(s, koff) do {                                              \
            _Pragma("unroll")                                                         \
            for (int mi = 0; mi < 4; mi++)                                            \
                ldsm_x4(as_h + mi * (16 * ROWB) + (koff),                             \
                        ah[s][mi][0], ah[s][mi][1], ah[s][mi][2], ah[s][mi][3]);      \
            _Pragma("unroll")                                                         \
            for (int mi = 0; mi < 4; mi++)                                            \
                ldsm_x4(as_l + mi * (16 * ROWB) + (koff),                             \
                        al[s][mi][0], al[s][mi][1], al[s][mi][2], al[s][mi][3]);      \
            _Pragma("unroll")                                                         \
            for (int p = 0; p < 2; p++) {                                             \
                uint32_t r0, r1, r2, r3;                                              \
                ldsm_x4(bs_h + p * (16 * ROWB) + (koff), r0, r1, r2, r3);             \
                bh[s][2 * p][0] = r0; bh[s][2 * p][1] = r1;                           \
                bh[s][2 * p + 1][0] = r2; bh[s][2 * p + 1][1] = r3;                   \
            }                                                                         \
            _Pragma("unroll")                                                         \
            for (int p = 0; p < 2; p++) {                                             \
                uint32_t r0, r1, r2, r3;                                              \
                ldsm_x4(bs_l + p * (16 * ROWB) + (koff), r0, r1, r2, r3);             \
                bl[s][2 * p][0] = r0; bl[s][2 * p][1] = r1;                           \
                bl[s][2 * p + 1][0] = r2; bl[s][2 * p + 1][1] = r3;                   \
            }                                                                         \
        } while (0)

        LOAD_FRAGS(0, 0);

        #pragma unroll
        for (int k0 = 0; k0 < 8; k0++) {
            const int cur = k0 & 1;
            if (k0 < 7) {
                const int nxt = cur ^ 1;
                LOAD_FRAGS(nxt, (uint32_t)(k0 + 1) * 32u);
            }
            #pragma unroll
            for (int mi = 0; mi < 4; mi++) {
                #pragma unroll
                for (int ni = 0; ni < 4; ni++) {
                    mma16816(c[mi][ni], ah[cur][mi], bh[cur][ni]);
                    mma16816(c[mi][ni], ah[cur][mi], bl[cur][ni]);
                    mma16816(c[mi][ni], al[cur][mi], bh[cur][ni]);
                }
            }
        }
        #undef LOAD_FRAGS

        // ---- epilogue ----
        #pragma unroll
        for (int mi = 0; mi < 4; mi++) {
            int row0 = mt * 128 + warp_m * 64 + mi * 16 + (lane >> 2);
            int row1 = row0 + 8;
            #pragma unroll
            for (int ni = 0; ni < 4; ni++) {
                int col = warp_n * 32 + ni * 8 + (lane & 3) * 2;
                if (ct < 8) {
                    if (row0 < NN)
                        *(float2*)(g_xw + (size_t)row0 * 1024 + ct * 128 + col) =
                            make_float2(c[mi][ni][0], c[mi][ni][1]);
                    if (row1 < NN)
                        *(float2*)(g_xw + (size_t)row1 * 1024 + ct * 128 + col) =
                            make_float2(c[mi][ni][2], c[mi][ni][3]);
                } else {
                    if (row0 < NN)
                        *(float2*)(outroot + (size_t)row0 * 128 + col) =
                            make_float2(c[mi][ni][0] + bv[ni].x, c[mi][ni][1] + bv[ni].y);
                    if (row1 < NN)
                        *(float2*)(outroot + (size_t)row1 * 128 + col) =
                            make_float2(c[mi][ni][2] + bv[ni].x, c[mi][ni][3] + bv[ni].y);
                }
            }
        }

        CP_WAIT0();
        __syncthreads();
    }
}

// ---------------- edge aggregation: one warp per edge, vector red ----------------
__global__ void edge_agg_kernel(const int* __restrict__ src, const int* __restrict__ dst,
                                const int* __restrict__ rel, int layer) {
    float* __restrict__ hacc = (layer == 0) ? g_hacc0 : g_hacc1;
    int gwarp = (blockIdx.x * blockDim.x + threadIdx.x) >> 5;
    int lane = threadIdx.x & 31;
    if (gwarp >= EE) return;
    int s = src[gwarp];
    int d = dst[gwarp];
    int r = rel[gwarp];
    int c = g_cnt[d * RR + r];
    float coef = 1.0f / (float)max(c, 1);
    float4 v = *(const float4*)(g_xw + (size_t)s * 1024 + r * 128 + lane * 4);
    float* o = hacc + (size_t)d * 128 + lane * 4;
    asm volatile("red.global.add.v4.f32 [%0], {%1, %2, %3, %4};"
                 :: "l"(o), "f"(v.x * coef), "f"(v.y * coef), "f"(v.z * coef), "f"(v.w * coef)
                 : "memory");
}

// ---------------- pooling: sum relu(h2) per graph ----------------
__global__ void pool_kernel(const int* __restrict__ batch) {
    int i = blockIdx.x * blockDim.x + threadIdx.x;
    if (i >= NN * HD) return;
    int n = i >> 7, h = i & 127;
    float v = fmaxf(g_hacc1[i], 0.0f);
    int g = batch[n];
    asm volatile("red.global.add.f32 [%0], %1;" :: "l"(&g_pool[g * HD + h]), "f"(v) : "memory");
    if (h == 0)
        asm volatile("red.global.add.f32 [%0], %1;" :: "l"(&g_pcnt[g]), "f"(1.0f) : "memory");
}

// ---------------- head ----------------
__global__ void final_kernel(const float* __restrict__ linW, const float* __restrict__ linb,
                             float* __restrict__ out) {
    int g = blockIdx.x;
    int tid = threadIdx.x;  // 128
    __shared__ float p[HD];
    float cnt = fmaxf(g_pcnt[g], 1.0f);
    p[tid] = g_pool[g * HD + tid] / cnt;
    __syncthreads();
    if (tid < NC) {
        float s = linb[tid];
        #pragma unroll 8
        for (int h = 0; h < HD; h++) s = fmaf(p[h], linW[h * NC + tid], s);
        out[g * NC + tid] = s;
    }
}

// ---------------- launch ----------------
extern "C" void kernel_launch(void* const* d_in, const int* in_sizes, int n_in,
                              void* d_out, int out_size) {
    const float* x     = (const float*)d_in[0];
    const int*   eidx  = (const int*)d_in[1];
    const int*   etype = (const int*)d_in[2];
    const int*   batch = (const int*)d_in[3];
    const float* W1    = (const float*)d_in[4];
    const float* root1 = (const float*)d_in[5];
    const float* b1    = (const float*)d_in[6];
    const float* W2    = (const float*)d_in[7];
    const float* root2 = (const float*)d_in[8];
    const float* b2    = (const float*)d_in[9];
    const float* linW  = (const float*)d_in[10];
    const float* linb  = (const float*)d_in[11];
    float* out = (float*)d_out;

    const int* src = eidx;
    const int* dst = eidx + EE;

    static bool attr_done = false;
    if (!attr_done) {
        cudaFuncSetAttribute(gemm_mma_kernel, cudaFuncAttributeMaxDynamicSharedMemorySize, SMEM_TOTAL);
        attr_done = true;
    }

    // structure-dependent counts (shared by both layers)
    zero_int_kernel<<<(NN * RR + 255) / 256, 256>>>(NN * RR);
    count_kernel<<<(EE + 255) / 256, 256>>>(dst, etype);

    int edge_blocks = (EE * 32 + 255) / 256;
    int pack_blocks = (9 * 128 * 128 + 255) / 256;

    // layer 1
    pack_w_kernel<<<pack_blocks, 256>>>(W1, root1);
    gemm_mma_kernel<<<NTILES, 256, SMEM_TOTAL>>>(x, b1, 0);
    edge_agg_kernel<<<edge_blocks, 256>>>(src, dst, etype, 0);

    // layer 2 (relu of layer-1 fused into GEMM A-load)
    pack_w_kernel<<<pack_blocks, 256>>>(W2, root2);
    gemm_mma_kernel<<<NTILES, 256, SMEM_TOTAL>>>(x, b2, 1);
    edge_agg_kernel<<<edge_blocks, 256>>>(src, dst, etype, 1);

    // pooling + head (relu of layer-2 fused into pooling read)
    zero_pool_kernel<<<(NG * HD + 255) / 256, 256>>>();
    pool_kernel<<<(NN * HD + 255) / 256, 256>>>(batch);
    final_kernel<<<NG, 128>>>(linW, linb, out);
}